// round 11
// baseline (speedup 1.0000x reference)
#include <cuda_runtime.h>
#include <math_constants.h>

// contributions: [S=256, P=2000, C=200] fp32, row-major (c contiguous).
// Per (s, c) column along P: zero the top-4 (stable ties -> lower p), pass rest.
//
// R10: DRAM-locality restructure. Kernel1: block = (sample, P-segment of 125
// rows), 224 threads, thread t<200 owns column c=t. The block streams its
// 100KB segment SEQUENTIALLY (whole 800B rows at a time) -> long contiguous
// read and write streams per block for DRAM row-buffer locality. Per-segment
// top-4 candidates go to __device__ scratch. Kernel2: one thread per column
// merges 16x4 candidates (stable: value desc, index asc) and patches 4 zeros.
// Kernel ordering guarantees copy-before-patch.

static constexpr int S = 256;
static constexpr int P = 2000;
static constexpr int C = 200;
static constexpr int NCOL = S * C;            // 51200 columns
static constexpr int SEG  = 16;               // P-segments per sample
static constexpr int PSEG = P / SEG;          // 125
static constexpr int U    = 5;                // 125 = 25 * 5
static constexpr int NB   = PSEG / U;         // 25 batches
static constexpr int BLK1 = 224;              // 7 warps; threads 200..223 idle
static constexpr int GRID1 = S * SEG;         // 4096 blocks
static constexpr int BLK2 = 256;
static constexpr int GRID2 = NCOL / BLK2;     // 200 blocks

// scratch: [s][seg][rank][c]  (c contiguous -> coalesced in both kernels)
__device__ float g_sv[S * SEG * 4 * C];
__device__ int   g_si[S * SEG * 4 * C];

__global__ void __launch_bounds__(BLK1)
k1_scan_copy(const float* __restrict__ in, float* __restrict__ out) {
    const int b   = blockIdx.x;
    const int s   = b >> 4;                   // sample
    const int seg = b & 15;                   // P-segment
    const int c   = threadIdx.x;              // column (if < 200)
    const bool active = (c < C);

    const int p0 = seg * PSEG;
    const float* __restrict__ ipp = in  + (size_t)s * P * C + (size_t)p0 * C + (active ? c : 0);
    float*       __restrict__ opp = out + (size_t)s * P * C + (size_t)p0 * C + (active ? c : 0);

    float t0 = -CUDART_INF_F, t1 = -CUDART_INF_F,
          t2 = -CUDART_INF_F, t3 = -CUDART_INF_F;
    int   i0 = 0, i1 = 0, i2 = 0, i3 = 0;

    int pbase = p0;
    if (active) {
        for (int it = 0; it < NB; it++) {
            float v[U];
            #pragma unroll
            for (int u = 0; u < U; u++)
                v[u] = ipp[u * C];            // immediate offsets
            #pragma unroll
            for (int u = 0; u < U; u++)
                opp[u * C] = v[u];

            // batch screen: one branch per 5 elements
            float mx = fmaxf(fmaxf(fmaxf(v[0], v[1]), fmaxf(v[2], v[3])), v[4]);

            if (mx > t3) {
                #pragma unroll
                for (int u = 0; u < U; u++) {
                    float vv = v[u];
                    if (vv > t3) {            // short branchless insert
                        const int pp = pbase + u;
                        const bool c0 = vv > t0;
                        const bool c1 = vv > t1;
                        const bool c2 = vv > t2;
                        float nt0 = c0 ? vv : t0;           int ni0 = c0 ? pp : i0;
                        float nt1 = c0 ? t0 : (c1 ? vv : t1);
                        int   ni1 = c0 ? i0 : (c1 ? pp : i1);
                        float nt2 = c1 ? t1 : (c2 ? vv : t2);
                        int   ni2 = c1 ? i1 : (c2 ? pp : i2);
                        float nt3 = c2 ? t2 : vv;           int ni3 = c2 ? i2 : pp;
                        t0 = nt0; t1 = nt1; t2 = nt2; t3 = nt3;
                        i0 = ni0; i1 = ni1; i2 = ni2; i3 = ni3;
                    }
                }
            }
            ipp += U * C;
            opp += U * C;
            pbase += U;
        }

        const size_t base = (size_t)b * (4 * C) + c;
        g_sv[base + 0 * C] = t0;  g_si[base + 0 * C] = i0;
        g_sv[base + 1 * C] = t1;  g_si[base + 1 * C] = i1;
        g_sv[base + 2 * C] = t2;  g_si[base + 2 * C] = i2;
        g_sv[base + 3 * C] = t3;  g_si[base + 3 * C] = i3;
    }
}

__global__ void __launch_bounds__(BLK2)
k2_merge_patch(float* __restrict__ out) {
    const int col = blockIdx.x * BLK2 + threadIdx.x;   // 0..51199
    const int s = col / C;
    const int c = col - s * C;

    float m0 = -CUDART_INF_F, m1 = -CUDART_INF_F,
          m2 = -CUDART_INF_F, m3 = -CUDART_INF_F;
    int   j0 = 0x7fffffff, j1 = 0x7fffffff,
          j2 = 0x7fffffff, j3 = 0x7fffffff;

    #pragma unroll 4
    for (int seg = 0; seg < SEG; seg++) {
        const size_t base = ((size_t)(s * SEG + seg)) * (4 * C) + c;
        #pragma unroll
        for (int r = 0; r < 4; r++) {
            float v = g_sv[base + (size_t)r * C];
            int   i = g_si[base + (size_t)r * C];
            // stable order: value desc, index asc
            if (v > m3 || (v == m3 && i < j3)) {
                if (v > m0 || (v == m0 && i < j0)) {
                    m3 = m2; j3 = j2; m2 = m1; j2 = j1; m1 = m0; j1 = j0;
                    m0 = v;  j0 = i;
                } else if (v > m1 || (v == m1 && i < j1)) {
                    m3 = m2; j3 = j2; m2 = m1; j2 = j1;
                    m1 = v;  j1 = i;
                } else if (v > m2 || (v == m2 && i < j2)) {
                    m3 = m2; j3 = j2;
                    m2 = v;  j2 = i;
                } else {
                    m3 = v;  j3 = i;
                }
            }
        }
    }

    float* opc = out + (size_t)s * P * C + c;
    opc[(size_t)j0 * C] = 0.0f;
    opc[(size_t)j1 * C] = 0.0f;
    opc[(size_t)j2 * C] = 0.0f;
    opc[(size_t)j3 * C] = 0.0f;
}

extern "C" void kernel_launch(void* const* d_in, const int* in_sizes, int n_in,
                              void* d_out, int out_size) {
    (void)in_sizes; (void)n_in; (void)out_size;
    const float* in  = (const float*)d_in[0];
    float*       out = (float*)d_out;
    k1_scan_copy<<<GRID1, BLK1>>>(in, out);
    k2_merge_patch<<<GRID2, BLK2>>>(out);
}

// round 12
// speedup vs baseline: 1.1143x; 1.1143x over previous
#include <cuda_runtime.h>
#include <math_constants.h>

// contributions: [S=256, P=2000, C=200] fp32, row-major (c contiguous).
// Per (s, c) column along P: zero the top-4 (stable ties -> lower p), pass rest.
//
// R11: R10's streaming k1 (block = (sample, P-segment), whole 800B rows,
// sequential 200KB stream per block -> best measured DRAM rate) with SEG=8
// (half the scratch) and a latency-optimized k2 (all 64 candidate loads
// issued up-front for MLP, then merge + patch).

static constexpr int S = 256;
static constexpr int P = 2000;
static constexpr int C = 200;
static constexpr int NCOL = S * C;            // 51200 columns
static constexpr int SEG  = 8;                // P-segments per sample
static constexpr int PSEG = P / SEG;          // 250
static constexpr int U    = 5;                // 250 = 50 * 5
static constexpr int NB   = PSEG / U;         // 50 batches
static constexpr int BLK1 = 224;              // 7 warps; threads 200..223 idle
static constexpr int GRID1 = S * SEG;         // 2048 blocks
static constexpr int BLK2 = 256;
static constexpr int GRID2 = NCOL / BLK2;     // 200 blocks

// scratch: [s][seg][rank][c]  (c contiguous -> coalesced in both kernels)
__device__ float g_sv[S * SEG * 4 * C];
__device__ int   g_si[S * SEG * 4 * C];

__global__ void __launch_bounds__(BLK1)
k1_scan_copy(const float* __restrict__ in, float* __restrict__ out) {
    const int b   = blockIdx.x;
    const int s   = b >> 3;                   // sample
    const int seg = b & 7;                    // P-segment
    const int c   = threadIdx.x;              // column (if < 200)
    if (c >= C) return;

    const int p0 = seg * PSEG;
    const float* __restrict__ ipp = in  + (size_t)s * P * C + (size_t)p0 * C + c;
    float*       __restrict__ opp = out + (size_t)s * P * C + (size_t)p0 * C + c;

    float t0 = -CUDART_INF_F, t1 = -CUDART_INF_F,
          t2 = -CUDART_INF_F, t3 = -CUDART_INF_F;
    int   i0 = 0, i1 = 0, i2 = 0, i3 = 0;

    int pbase = p0;
    for (int it = 0; it < NB; it++) {
        float v[U];
        #pragma unroll
        for (int u = 0; u < U; u++)
            v[u] = ipp[u * C];                // immediate offsets
        #pragma unroll
        for (int u = 0; u < U; u++)
            opp[u * C] = v[u];

        // batch screen: one branch per 5 elements
        float mx = fmaxf(fmaxf(fmaxf(v[0], v[1]), fmaxf(v[2], v[3])), v[4]);

        if (mx > t3) {
            #pragma unroll
            for (int u = 0; u < U; u++) {
                float vv = v[u];
                if (vv > t3) {                // short branchless insert
                    const int pp = pbase + u;
                    const bool c0 = vv > t0;
                    const bool c1 = vv > t1;
                    const bool c2 = vv > t2;
                    float nt0 = c0 ? vv : t0;           int ni0 = c0 ? pp : i0;
                    float nt1 = c0 ? t0 : (c1 ? vv : t1);
                    int   ni1 = c0 ? i0 : (c1 ? pp : i1);
                    float nt2 = c1 ? t1 : (c2 ? vv : t2);
                    int   ni2 = c1 ? i1 : (c2 ? pp : i2);
                    float nt3 = c2 ? t2 : vv;           int ni3 = c2 ? i2 : pp;
                    t0 = nt0; t1 = nt1; t2 = nt2; t3 = nt3;
                    i0 = ni0; i1 = ni1; i2 = ni2; i3 = ni3;
                }
            }
        }
        ipp += U * C;
        opp += U * C;
        pbase += U;
    }

    const size_t base = (size_t)b * (4 * C) + c;
    g_sv[base + 0 * C] = t0;  g_si[base + 0 * C] = i0;
    g_sv[base + 1 * C] = t1;  g_si[base + 1 * C] = i1;
    g_sv[base + 2 * C] = t2;  g_si[base + 2 * C] = i2;
    g_sv[base + 3 * C] = t3;  g_si[base + 3 * C] = i3;
}

__global__ void __launch_bounds__(BLK2)
k2_merge_patch(float* __restrict__ out) {
    const int col = blockIdx.x * BLK2 + threadIdx.x;   // 0..51199
    const int s = col / C;
    const int c = col - s * C;

    // Load ALL 32 candidates (val+idx) up-front: 64 independent coalesced
    // loads in flight -> latency fully overlapped.
    float cv[SEG * 4];
    int   ci[SEG * 4];
    #pragma unroll
    for (int seg = 0; seg < SEG; seg++) {
        const size_t base = ((size_t)(s * SEG + seg)) * (4 * C) + c;
        #pragma unroll
        for (int r = 0; r < 4; r++) {
            cv[seg * 4 + r] = g_sv[base + (size_t)r * C];
            ci[seg * 4 + r] = g_si[base + (size_t)r * C];
        }
    }

    float m0 = -CUDART_INF_F, m1 = -CUDART_INF_F,
          m2 = -CUDART_INF_F, m3 = -CUDART_INF_F;
    int   j0 = 0x7fffffff, j1 = 0x7fffffff,
          j2 = 0x7fffffff, j3 = 0x7fffffff;

    #pragma unroll
    for (int k = 0; k < SEG * 4; k++) {
        float v = cv[k];
        int   i = ci[k];
        // stable order: value desc, index asc
        if (v > m3 || (v == m3 && i < j3)) {
            if (v > m0 || (v == m0 && i < j0)) {
                m3 = m2; j3 = j2; m2 = m1; j2 = j1; m1 = m0; j1 = j0;
                m0 = v;  j0 = i;
            } else if (v > m1 || (v == m1 && i < j1)) {
                m3 = m2; j3 = j2; m2 = m1; j2 = j1;
                m1 = v;  j1 = i;
            } else if (v > m2 || (v == m2 && i < j2)) {
                m3 = m2; j3 = j2;
                m2 = v;  j2 = i;
            } else {
                m3 = v;  j3 = i;
            }
        }
    }

    float* opc = out + (size_t)s * P * C + c;
    opc[(size_t)j0 * C] = 0.0f;
    opc[(size_t)j1 * C] = 0.0f;
    opc[(size_t)j2 * C] = 0.0f;
    opc[(size_t)j3 * C] = 0.0f;
}

extern "C" void kernel_launch(void* const* d_in, const int* in_sizes, int n_in,
                              void* d_out, int out_size) {
    (void)in_sizes; (void)n_in; (void)out_size;
    const float* in  = (const float*)d_in[0];
    float*       out = (float*)d_out;
    k1_scan_copy<<<GRID1, BLK1>>>(in, out);
    k2_merge_patch<<<GRID2, BLK2>>>(out);
}

// round 14
// speedup vs baseline: 1.2323x; 1.1059x over previous
#include <cuda_runtime.h>
#include <math_constants.h>

// contributions: [S=256, P=2000, C=200] fp32, row-major (c contiguous).
// Per (s, c) column along P: zero the top-4 (stable ties -> lower p), pass rest.
//
// R13 (= R12 resubmit; previous round died to a container infra failure).
// Fused full-row streaming: block = one sample (1024 threads = 5 P-segments
// x 200 columns). The block streams its 1.6MB sample as whole 800B rows (5
// sequential sub-streams) -> the DRAM page locality that measured 5.9TB/s in
// R10's k1, but with the cross-segment merge done in-block via 32KB smem:
// no scratch round-trip, no second kernel. 256 blocks, 2 CTAs/SM, one wave.
// launch_bounds relaxed to avoid any forced-spill risk.

static constexpr int S    = 256;
static constexpr int P    = 2000;
static constexpr int C    = 200;
static constexpr int SEG  = 5;                // P-segments per sample (in-block)
static constexpr int PSEG = P / SEG;          // 400
static constexpr int U    = 10;               // 400 = 40 * 10
static constexpr int NB   = PSEG / U;         // 40 batches
static constexpr int BLK  = 1024;             // 5*200=1000 active
static constexpr int ACT  = SEG * C;          // 1000
static constexpr int GRID = S;                // 256 blocks

__global__ void __launch_bounds__(BLK)
numproto_topk_zero(const float* __restrict__ in, float* __restrict__ out) {
    const int tid = threadIdx.x;
    const int s   = blockIdx.x;
    const int seg = tid / C;                  // 0..4 (tid<1000)
    const int c   = tid - seg * C;            // 0..199

    __shared__ float sv[SEG][4][C];
    __shared__ int   si[SEG][4][C];

    if (tid < ACT) {
        const int p0 = seg * PSEG;
        const float* __restrict__ ipp = in  + (size_t)s * P * C + (size_t)p0 * C + c;
        float*       __restrict__ opp = out + (size_t)s * P * C + (size_t)p0 * C + c;

        float t0 = -CUDART_INF_F, t1 = -CUDART_INF_F,
              t2 = -CUDART_INF_F, t3 = -CUDART_INF_F;
        int   i0 = 0, i1 = 0, i2 = 0, i3 = 0;

        int pbase = p0;
        for (int it = 0; it < NB; it++) {
            float v[U];
            #pragma unroll
            for (int u = 0; u < U; u++)
                v[u] = ipp[u * C];            // immediate offsets
            #pragma unroll
            for (int u = 0; u < U; u++)
                opp[u * C] = v[u];

            // batch screen: one branch per 10 elements
            float m01 = fmaxf(v[0], v[1]);
            float m23 = fmaxf(v[2], v[3]);
            float m45 = fmaxf(v[4], v[5]);
            float m67 = fmaxf(v[6], v[7]);
            float m89 = fmaxf(v[8], v[9]);
            float mx  = fmaxf(fmaxf(fmaxf(m01, m23), fmaxf(m45, m67)), m89);

            if (mx > t3) {
                #pragma unroll
                for (int u = 0; u < U; u++) {
                    float vv = v[u];
                    if (vv > t3) {            // short branchless insert
                        const int pp = pbase + u;
                        const bool c0 = vv > t0;
                        const bool c1 = vv > t1;
                        const bool c2 = vv > t2;
                        float nt0 = c0 ? vv : t0;           int ni0 = c0 ? pp : i0;
                        float nt1 = c0 ? t0 : (c1 ? vv : t1);
                        int   ni1 = c0 ? i0 : (c1 ? pp : i1);
                        float nt2 = c1 ? t1 : (c2 ? vv : t2);
                        int   ni2 = c1 ? i1 : (c2 ? pp : i2);
                        float nt3 = c2 ? t2 : vv;           int ni3 = c2 ? i2 : pp;
                        t0 = nt0; t1 = nt1; t2 = nt2; t3 = nt3;
                        i0 = ni0; i1 = ni1; i2 = ni2; i3 = ni3;
                    }
                }
            }
            ipp += U * C;
            opp += U * C;
            pbase += U;
        }

        sv[seg][0][c] = t0;  si[seg][0][c] = i0;
        sv[seg][1][c] = t1;  si[seg][1][c] = i1;
        sv[seg][2][c] = t2;  si[seg][2][c] = i2;
        sv[seg][3][c] = t3;  si[seg][3][c] = i3;
    }

    __syncthreads();   // orders this block's copy-stores before the patch

    if (tid < C) {
        float* opc = out + (size_t)s * P * C + tid;

        float m0 = -CUDART_INF_F, m1 = -CUDART_INF_F,
              m2 = -CUDART_INF_F, m3 = -CUDART_INF_F;
        int   j0 = 0x7fffffff, j1 = 0x7fffffff,
              j2 = 0x7fffffff, j3 = 0x7fffffff;

        #pragma unroll
        for (int sg = 0; sg < SEG; sg++) {
            #pragma unroll
            for (int k = 0; k < 4; k++) {
                float v = sv[sg][k][tid];
                int   i = si[sg][k][tid];
                // stable order: value desc, index asc
                if (v > m3 || (v == m3 && i < j3)) {
                    if (v > m0 || (v == m0 && i < j0)) {
                        m3 = m2; j3 = j2; m2 = m1; j2 = j1; m1 = m0; j1 = j0;
                        m0 = v;  j0 = i;
                    } else if (v > m1 || (v == m1 && i < j1)) {
                        m3 = m2; j3 = j2; m2 = m1; j2 = j1;
                        m1 = v;  j1 = i;
                    } else if (v > m2 || (v == m2 && i < j2)) {
                        m3 = m2; j3 = j2;
                        m2 = v;  j2 = i;
                    } else {
                        m3 = v;  j3 = i;
                    }
                }
            }
        }
        opc[(size_t)j0 * C] = 0.0f;
        opc[(size_t)j1 * C] = 0.0f;
        opc[(size_t)j2 * C] = 0.0f;
        opc[(size_t)j3 * C] = 0.0f;
    }
}

extern "C" void kernel_launch(void* const* d_in, const int* in_sizes, int n_in,
                              void* d_out, int out_size) {
    (void)in_sizes; (void)n_in; (void)out_size;
    const float* in  = (const float*)d_in[0];
    float*       out = (float*)d_out;
    numproto_topk_zero<<<GRID, BLK>>>(in, out);
}